// round 3
// baseline (speedup 1.0000x reference)
#include <cuda_runtime.h>
#include <math.h>
#include <stdint.h>

#define BATCH   4096
#define D_MODEL 1024
#define NT      64
#define RANK    8
#define NR      (NT * RANK)   /* 512 */

// Scratch (device globals: no allocation allowed)
__device__ float g_Y[(size_t)BATCH * NR];      // gated Vx, (batch, n*r)
__device__ float g_Wt[(size_t)D_MODEL * NR];   // U transposed: Wt[d][k] = U[n,d,r]

__device__ __forceinline__ uint32_t f2tf32(float f) {
    uint32_t u;
    asm("cvt.rna.tf32.f32 %0, %1;" : "=r"(u) : "f"(f));
    return u;
}

__device__ __forceinline__ void mma_tf32(float c[4], const uint32_t a[4], const uint32_t b[2]) {
    asm volatile(
        "mma.sync.aligned.m16n8k8.row.col.f32.tf32.tf32.f32 "
        "{%0,%1,%2,%3}, {%4,%5,%6,%7}, {%8,%9}, {%0,%1,%2,%3};"
        : "+f"(c[0]), "+f"(c[1]), "+f"(c[2]), "+f"(c[3])
        : "r"(a[0]), "r"(a[1]), "r"(a[2]), "r"(a[3]), "r"(b[0]), "r"(b[1]));
}

__device__ __forceinline__ void cp16(void* smem_dst, const void* gmem_src) {
    uint32_t sa = (uint32_t)__cvta_generic_to_shared(smem_dst);
    asm volatile("cp.async.cg.shared.global [%0], [%1], 16;\n" :: "r"(sa), "l"(gmem_src));
}

// ---------------------------------------------------------------------------
// NT GEMM via tf32 mma.sync, cp.async double-buffered:
//   C[M,N] = A[M,K] @ B[N,K]^T
// MODE 0: gate epilogue  v = relu(acc - bias[col])
// MODE 1: scale epilogue v = acc * gate[row*NT + col/8] -> g_Y
// MODE 2: plain          A := g_Y, B := g_Wt
// ---------------------------------------------------------------------------
template <int BM, int BN, int BK, int WY, int WX, int MODE>
__global__ __launch_bounds__(WY * WX * 32)
void gemm_tf32(const float* __restrict__ A, const float* __restrict__ B,
               float* __restrict__ C, int M, int N, int K,
               const float* __restrict__ bias, const float* __restrict__ gate)
{
    constexpr int THREADS = WY * WX * 32;
    constexpr int WM = BM / WY;
    constexpr int WN = BN / WX;
    constexpr int MI = WM / 16;
    constexpr int NI = WN / 8;
    constexpr int PAD = 4;
    constexpr int ACH = BM * (BK / 4);   // 16B chunks in A tile
    constexpr int BCH = BN * (BK / 4);

    __shared__ float As[2][BM][BK + PAD];
    __shared__ float Bs[2][BN][BK + PAD];

    const int tid  = threadIdx.x;
    const int wid  = tid >> 5;
    const int lane = tid & 31;
    const int wy   = wid / WX;
    const int wx   = wid % WX;
    const int lq   = lane >> 2;   // 0..7
    const int lr   = lane & 3;    // 0..3
    const int row0 = blockIdx.y * BM;
    const int col0 = blockIdx.x * BN;

    const float* Aptr = (MODE == 2) ? g_Y  : A;
    const float* Bptr = (MODE == 2) ? g_Wt : B;

    float acc[MI][NI][4];
#pragma unroll
    for (int mi = 0; mi < MI; mi++)
#pragma unroll
        for (int ni = 0; ni < NI; ni++)
#pragma unroll
            for (int j = 0; j < 4; j++) acc[mi][ni][j] = 0.0f;

    auto load_tile = [&](int stage, int k0) {
#pragma unroll
        for (int i = tid; i < ACH; i += THREADS) {
            int r = i / (BK / 4), c4 = i % (BK / 4);
            cp16(&As[stage][r][c4 * 4], &Aptr[(size_t)(row0 + r) * K + k0 + c4 * 4]);
        }
#pragma unroll
        for (int i = tid; i < BCH; i += THREADS) {
            int r = i / (BK / 4), c4 = i % (BK / 4);
            cp16(&Bs[stage][r][c4 * 4], &Bptr[(size_t)(col0 + r) * K + k0 + c4 * 4]);
        }
    };

    const int NTILES = K / BK;

    load_tile(0, 0);
    asm volatile("cp.async.commit_group;\n");

    for (int t = 0; t < NTILES; t++) {
        if (t + 1 < NTILES) {
            load_tile((t + 1) & 1, (t + 1) * BK);
            asm volatile("cp.async.commit_group;\n");
            asm volatile("cp.async.wait_group 1;\n");
        } else {
            asm volatile("cp.async.wait_group 0;\n");
        }
        __syncthreads();

        const int s = t & 1;
#pragma unroll
        for (int kk = 0; kk < BK; kk += 8) {
            uint32_t af[MI][4], bf[NI][2];
#pragma unroll
            for (int mi = 0; mi < MI; mi++) {
                int r = wy * WM + mi * 16 + lq;
                af[mi][0] = f2tf32(As[s][r][kk + lr]);
                af[mi][1] = f2tf32(As[s][r + 8][kk + lr]);
                af[mi][2] = f2tf32(As[s][r][kk + lr + 4]);
                af[mi][3] = f2tf32(As[s][r + 8][kk + lr + 4]);
            }
#pragma unroll
            for (int ni = 0; ni < NI; ni++) {
                int c = wx * WN + ni * 8 + lq;
                bf[ni][0] = f2tf32(Bs[s][c][kk + lr]);
                bf[ni][1] = f2tf32(Bs[s][c][kk + lr + 4]);
            }
#pragma unroll
            for (int mi = 0; mi < MI; mi++)
#pragma unroll
                for (int ni = 0; ni < NI; ni++)
                    mma_tf32(acc[mi][ni], af[mi], bf[ni]);
        }
        __syncthreads();
    }

    // ---- epilogue ----
#pragma unroll
    for (int mi = 0; mi < MI; mi++) {
        int r0 = row0 + wy * WM + mi * 16 + lq;   // rows r0 and r0+8
#pragma unroll
        for (int ni = 0; ni < NI; ni++) {
            int c = col0 + wx * WN + ni * 8 + 2 * lr;
            float v0 = acc[mi][ni][0], v1 = acc[mi][ni][1];
            float v2 = acc[mi][ni][2], v3 = acc[mi][ni][3];
            if constexpr (MODE == 0) {
                float b0 = bias[c], b1 = bias[c + 1];
                v0 -= b0; v1 -= b1; v2 -= b0; v3 -= b1;
                v0 = v0 > 0.f ? v0 : 0.f;  v1 = v1 > 0.f ? v1 : 0.f;
                v2 = v2 > 0.f ? v2 : 0.f;  v3 = v3 > 0.f ? v3 : 0.f;
                *(float2*)&C[(size_t)r0 * N + c]       = make_float2(v0, v1);
                *(float2*)&C[(size_t)(r0 + 8) * N + c] = make_float2(v2, v3);
            } else if constexpr (MODE == 1) {
                int gc = (col0 + wx * WN + ni * 8) >> 3;
                float g0 = gate[(size_t)r0 * NT + gc];
                float g1 = gate[(size_t)(r0 + 8) * NT + gc];
                *(float2*)&g_Y[(size_t)r0 * N + c]       = make_float2(v0 * g0, v1 * g0);
                *(float2*)&g_Y[(size_t)(r0 + 8) * N + c] = make_float2(v2 * g1, v3 * g1);
            } else {
                *(float2*)&C[(size_t)r0 * N + c]       = make_float2(v0, v1);
                *(float2*)&C[(size_t)(r0 + 8) * N + c] = make_float2(v2, v3);
            }
        }
    }
}

// Wt[d][k] = U[n, d, r] where k = n*RANK + r
__global__ void transpose_U(const float* __restrict__ U)
{
    int idx = blockIdx.x * 256 + threadIdx.x;
    int d = idx >> 9;
    int k = idx & (NR - 1);
    g_Wt[idx] = U[(size_t)(k >> 3) * (D_MODEL * RANK) + (size_t)d * RANK + (k & 7)];
}

__global__ void fro_norms(const float* __restrict__ U, const float* __restrict__ V,
                          float* __restrict__ fro)
{
    __shared__ float ssu[256];
    __shared__ float ssv[256];
    int n = blockIdx.x;
    float su = 0.0f, sv = 0.0f;
    for (int i = threadIdx.x; i < D_MODEL * RANK; i += 256) {
        float u = U[(size_t)n * (D_MODEL * RANK) + i];
        float v = V[(size_t)n * (D_MODEL * RANK) + i];
        su += u * u;
        sv += v * v;
    }
    ssu[threadIdx.x] = su;
    ssv[threadIdx.x] = sv;
    __syncthreads();
    for (int s = 128; s > 0; s >>= 1) {
        if (threadIdx.x < s) {
            ssu[threadIdx.x] += ssu[threadIdx.x + s];
            ssv[threadIdx.x] += ssv[threadIdx.x + s];
        }
        __syncthreads();
    }
    if (threadIdx.x == 0)
        fro[n] = sqrtf(ssu[0]) * sqrtf(ssv[0]) * rsqrtf((float)(D_MODEL * RANK));
}

extern "C" void kernel_launch(void* const* d_in, const int* in_sizes, int n_in,
                              void* d_out, int out_size)
{
    const float* x    = (const float*)d_in[0];
    const float* V    = (const float*)d_in[1];
    const float* U    = (const float*)d_in[2];
    const float* enc  = (const float*)d_in[3];
    const float* bias = (const float*)d_in[4];

    float* out  = (float*)d_out;
    float* gate = out + (size_t)BATCH * D_MODEL;
    float* fro  = gate + (size_t)BATCH * NT;

    // Phase 1: gate = relu(x @ enc^T - bias)   [4096 x 64, K=1024]
    gemm_tf32<64, 64, 16, 2, 2, 0>
        <<<dim3(1, BATCH / 64), 128>>>(x, enc, gate, BATCH, NT, D_MODEL, bias, nullptr);

    // Transpose U into Wt (independent of phase 1)
    transpose_U<<<(D_MODEL * NR) / 256, 256>>>(U);

    // Phase 2: Y = (x @ Vflat^T) * gate   [4096 x 512, K=1024] -> g_Y
    gemm_tf32<128, 128, 16, 2, 4, 1>
        <<<dim3(NR / 128, BATCH / 128), 256>>>(x, V, nullptr, BATCH, NR, D_MODEL, nullptr, gate);

    // Phase 3: out = Y @ Wt^T   [4096 x 1024, K=512]
    gemm_tf32<128, 128, 16, 2, 4, 2>
        <<<dim3(D_MODEL / 128, BATCH / 128), 256>>>(nullptr, nullptr, out, BATCH, D_MODEL, NR,
                                                    nullptr, nullptr);

    fro_norms<<<NT, 256>>>(U, V, fro);
}

// round 5
// speedup vs baseline: 1.2892x; 1.2892x over previous
#include <cuda_runtime.h>
#include <math.h>
#include <stdint.h>

#define BATCH   4096
#define D_MODEL 1024
#define NT      64
#define RANK    8
#define NR      512

// Scratch (device globals: no allocation allowed)
__device__ float g_Y[(size_t)BATCH * NR];     // gated Vx
__device__ float g_Wt[(size_t)D_MODEL * NR];  // U transposed: Wt[d][k] = U[n,d,r]
__device__ float g_pre[(size_t)BATCH * NT];   // split-K accumulator (zero-init, self-resetting)

__device__ __forceinline__ uint32_t f2tf32(float f) {
    uint32_t u;
    asm("cvt.rna.tf32.f32 %0, %1;" : "=r"(u) : "f"(f));
    return u;
}

__device__ __forceinline__ void mma_tf32(float c[4], const uint32_t a[4], const uint32_t b[2]) {
    asm volatile(
        "mma.sync.aligned.m16n8k8.row.col.f32.tf32.tf32.f32 "
        "{%0,%1,%2,%3}, {%4,%5,%6,%7}, {%8,%9}, {%0,%1,%2,%3};"
        : "+f"(c[0]), "+f"(c[1]), "+f"(c[2]), "+f"(c[3])
        : "r"(a[0]), "r"(a[1]), "r"(a[2]), "r"(a[3]), "r"(b[0]), "r"(b[1]));
}

// ---------------------------------------------------------------------------
// Double-buffered tf32 NT GEMM: C[M,N] = A[M,K] @ B[N,K]^T.  BM=128, BK=32,
// 256 threads (2x4 warps, warp tile 64 x BN/4).
// MODE 1: v = acc * gate[row][col/8] -> g_Y
// MODE 2: plain, A := g_Y, B := g_Wt -> C
// MODE 3: split-K partial: atomicAdd into g_pre (col0=0, koff=blockIdx.x*Kloop)
// ---------------------------------------------------------------------------
template <int BM, int BN, int BK, int MODE>
__global__ __launch_bounds__(256, 2)
void tc_gemm(const float* __restrict__ Ag, const float* __restrict__ Bg,
             float* __restrict__ Cg, int lda, int ldb, int Kloop, int ldc,
             const float* __restrict__ gate)
{
    constexpr int WY = 2, WX = 4;
    constexpr int WM = BM / WY;          // 64
    constexpr int WN = BN / WX;          // 32 or 16
    constexpr int MI = WM / 16;          // 4
    constexpr int NI = WN / 8;           // 4 or 2
    constexpr int RW = BK + 4;           // smem row words (pad 4)
    constexpr int SW = (BM + BN) * RW;   // words per stage
    constexpr int AC4 = BM * (BK / 4) / 256;   // float4 chunks/thread for A
    constexpr int BC4 = BN * (BK / 4) / 256;

    extern __shared__ uint32_t smu[];
#define AS(s, r, c) smu[(s) * SW + (r) * RW + (c)]
#define BS(s, r, c) smu[(s) * SW + BM * RW + (r) * RW + (c)]

    const int tid  = threadIdx.x;
    const int wid  = tid >> 5;
    const int lane = tid & 31;
    const int wy   = wid / WX;
    const int wx   = wid % WX;
    const int lq   = lane >> 2;
    const int lr   = lane & 3;
    const int row0 = blockIdx.y * BM;
    const int col0 = (MODE == 3) ? 0 : blockIdx.x * BN;
    const int koff = (MODE == 3) ? blockIdx.x * Kloop : 0;

    const float* A = (MODE == 2) ? g_Y  : Ag;
    const float* B = (MODE == 2) ? g_Wt : Bg;

    float acc[MI][NI][4];
#pragma unroll
    for (int mi = 0; mi < MI; mi++)
#pragma unroll
        for (int ni = 0; ni < NI; ni++)
#pragma unroll
            for (int j = 0; j < 4; j++) acc[mi][ni][j] = 0.0f;

    float4 va[AC4], vb[BC4];

    auto load_regs = [&](int t) {
        const int k0 = koff + t * BK;
#pragma unroll
        for (int j = 0; j < AC4; j++) {
            int ch = tid + j * 256;
            int r = ch >> 3, c4 = ch & 7;
            va[j] = *(const float4*)&A[(size_t)(row0 + r) * lda + k0 + c4 * 4];
        }
#pragma unroll
        for (int j = 0; j < BC4; j++) {
            int ch = tid + j * 256;
            int r = ch >> 3, c4 = ch & 7;
            vb[j] = *(const float4*)&B[(size_t)(col0 + r) * ldb + k0 + c4 * 4];
        }
    };
    auto cvt_sts = [&](int s) {
#pragma unroll
        for (int j = 0; j < AC4; j++) {
            int ch = tid + j * 256;
            int r = ch >> 3, c4 = ch & 7;
            uint4 u;
            u.x = f2tf32(va[j].x); u.y = f2tf32(va[j].y);
            u.z = f2tf32(va[j].z); u.w = f2tf32(va[j].w);
            *(uint4*)&AS(s, r, c4 * 4) = u;
        }
#pragma unroll
        for (int j = 0; j < BC4; j++) {
            int ch = tid + j * 256;
            int r = ch >> 3, c4 = ch & 7;
            uint4 u;
            u.x = f2tf32(vb[j].x); u.y = f2tf32(vb[j].y);
            u.z = f2tf32(vb[j].z); u.w = f2tf32(vb[j].w);
            *(uint4*)&BS(s, r, c4 * 4) = u;
        }
    };
    auto compute = [&](int s) {
#pragma unroll
        for (int kk = 0; kk < BK; kk += 8) {
            uint32_t af[MI][4], bf[NI][2];
#pragma unroll
            for (int mi = 0; mi < MI; mi++) {
                int r = wy * WM + mi * 16 + lq;
                af[mi][0] = AS(s, r, kk + lr);
                af[mi][1] = AS(s, r + 8, kk + lr);
                af[mi][2] = AS(s, r, kk + lr + 4);
                af[mi][3] = AS(s, r + 8, kk + lr + 4);
            }
#pragma unroll
            for (int ni = 0; ni < NI; ni++) {
                int c = wx * WN + ni * 8 + lq;
                bf[ni][0] = BS(s, c, kk + lr);
                bf[ni][1] = BS(s, c, kk + lr + 4);
            }
#pragma unroll
            for (int mi = 0; mi < MI; mi++)
#pragma unroll
                for (int ni = 0; ni < NI; ni++)
                    mma_tf32(acc[mi][ni], af[mi], bf[ni]);
        }
    };

    const int T = Kloop / BK;

    // prologue
    load_regs(0);
    cvt_sts(0);
    if (T > 1) load_regs(1);
    __syncthreads();

    for (int t = 0; t < T; t++) {
        compute(t & 1);                       // tensor pipe busy
        if (t + 1 < T) cvt_sts((t + 1) & 1);  // overlaps tensor drain
        if (t + 2 < T) load_regs(t + 2);      // hide gmem latency
        __syncthreads();
    }

    // ---- epilogue ----
#pragma unroll
    for (int mi = 0; mi < MI; mi++) {
        int r0 = row0 + wy * WM + mi * 16 + lq;
#pragma unroll
        for (int ni = 0; ni < NI; ni++) {
            int c = col0 + wx * WN + ni * 8 + 2 * lr;
            float v0 = acc[mi][ni][0], v1 = acc[mi][ni][1];
            float v2 = acc[mi][ni][2], v3 = acc[mi][ni][3];
            if constexpr (MODE == 1) {
                int gc = (col0 + wx * WN + ni * 8) >> 3;
                float g0 = gate[(size_t)r0 * NT + gc];
                float g1 = gate[(size_t)(r0 + 8) * NT + gc];
                *(float2*)&g_Y[(size_t)r0 * ldc + c]       = make_float2(v0 * g0, v1 * g0);
                *(float2*)&g_Y[(size_t)(r0 + 8) * ldc + c] = make_float2(v2 * g1, v3 * g1);
            } else if constexpr (MODE == 2) {
                *(float2*)&Cg[(size_t)r0 * ldc + c]       = make_float2(v0, v1);
                *(float2*)&Cg[(size_t)(r0 + 8) * ldc + c] = make_float2(v2, v3);
            } else {
                atomicAdd(&g_pre[(size_t)r0 * NT + c], v0);
                atomicAdd(&g_pre[(size_t)r0 * NT + c + 1], v1);
                atomicAdd(&g_pre[(size_t)(r0 + 8) * NT + c], v2);
                atomicAdd(&g_pre[(size_t)(r0 + 8) * NT + c + 1], v3);
            }
        }
    }
#undef AS
#undef BS
}

// gate = relu(pre - bias); reset pre to 0 for next replay (keeps graph replays correct)
__global__ void gate_relu(const float* __restrict__ bias, float* __restrict__ gate)
{
    int i = blockIdx.x * 256 + threadIdx.x;          // over BATCH*NT/4
    int c = (i * 4) & (NT - 1);
    float4 p = *(float4*)&g_pre[(size_t)i * 4];
    float4 b = *(const float4*)&bias[c];
    float4 o;
    float v0 = p.x - b.x, v1 = p.y - b.y, v2 = p.z - b.z, v3 = p.w - b.w;
    o.x = v0 > 0.f ? v0 : 0.f;  o.y = v1 > 0.f ? v1 : 0.f;
    o.z = v2 > 0.f ? v2 : 0.f;  o.w = v3 > 0.f ? v3 : 0.f;
    *(float4*)&gate[(size_t)i * 4] = o;
    *(float4*)&g_pre[(size_t)i * 4] = make_float4(0.f, 0.f, 0.f, 0.f);
}

// prep: blocks [0, 2048) transpose U -> g_Wt; blocks [2048, 2112) Frobenius norms
__global__ void prep(const float* __restrict__ U, const float* __restrict__ V,
                     float* __restrict__ fro)
{
    __shared__ float ssu[256];
    __shared__ float ssv[256];
    if (blockIdx.x < 2048) {
        int idx = blockIdx.x * 256 + threadIdx.x;
        int d = idx >> 9;
        int k = idx & (NR - 1);
        g_Wt[idx] = U[(size_t)(k >> 3) * (D_MODEL * RANK) + (size_t)d * RANK + (k & 7)];
    } else {
        int n = blockIdx.x - 2048;
        float su = 0.0f, sv = 0.0f;
        for (int i = threadIdx.x; i < D_MODEL * RANK; i += 256) {
            float u = U[(size_t)n * (D_MODEL * RANK) + i];
            float v = V[(size_t)n * (D_MODEL * RANK) + i];
            su += u * u;
            sv += v * v;
        }
        ssu[threadIdx.x] = su;
        ssv[threadIdx.x] = sv;
        __syncthreads();
        for (int s = 128; s > 0; s >>= 1) {
            if (threadIdx.x < s) {
                ssu[threadIdx.x] += ssu[threadIdx.x + s];
                ssv[threadIdx.x] += ssv[threadIdx.x + s];
            }
            __syncthreads();
        }
        if (threadIdx.x == 0)
            fro[n] = sqrtf(ssu[0]) * sqrtf(ssv[0]) * rsqrtf((float)(D_MODEL * RANK));
    }
}

extern "C" void kernel_launch(void* const* d_in, const int* in_sizes, int n_in,
                              void* d_out, int out_size)
{
    const float* x    = (const float*)d_in[0];
    const float* V    = (const float*)d_in[1];
    const float* U    = (const float*)d_in[2];
    const float* enc  = (const float*)d_in[3];
    const float* bias = (const float*)d_in[4];

    float* out  = (float*)d_out;
    float* gate = out + (size_t)BATCH * D_MODEL;
    float* fro  = gate + (size_t)BATCH * NT;

    constexpr int SM_P1 = 2 * (128 + 64) * 36 * 4;   // 55296
    constexpr int SM_P2 = 2 * (128 + 128) * 36 * 4;  // 73728

    cudaFuncSetAttribute(tc_gemm<128, 64, 32, 3>,
                         cudaFuncAttributeMaxDynamicSharedMemorySize, SM_P1);
    cudaFuncSetAttribute(tc_gemm<128, 128, 32, 1>,
                         cudaFuncAttributeMaxDynamicSharedMemorySize, SM_P2);
    cudaFuncSetAttribute(tc_gemm<128, 128, 32, 2>,
                         cudaFuncAttributeMaxDynamicSharedMemorySize, SM_P2);

    // Phase 1 (split-K x8): g_pre += x @ enc^T   [4096 x 64, K slices of 128]
    tc_gemm<128, 64, 32, 3><<<dim3(8, BATCH / 128), 256, SM_P1>>>(
        x, enc, nullptr, D_MODEL, D_MODEL, 128, 0, nullptr);

    // prep: transpose U + Frobenius norms (independent)
    prep<<<2048 + NT, 256>>>(U, V, fro);

    // Phase 1b: gate = relu(pre - bias), reset pre
    gate_relu<<<BATCH * NT / 4 / 256, 256>>>(bias, gate);

    // Phase 2: g_Y = (x @ V^T) * gate   [4096 x 512, K=1024]
    tc_gemm<128, 128, 32, 1><<<dim3(NR / 128, BATCH / 128), 256, SM_P2>>>(
        x, V, nullptr, D_MODEL, D_MODEL, D_MODEL, NR, gate);

    // Phase 3: out = g_Y @ g_Wt^T   [4096 x 1024, K=512]
    tc_gemm<128, 128, 32, 2><<<dim3(D_MODEL / 128, BATCH / 128), 256, SM_P2>>>(
        nullptr, nullptr, out, NR, NR, NR, D_MODEL, nullptr);
}